// round 3
// baseline (speedup 1.0000x reference)
#include <cuda_runtime.h>

// 2-layer LSTM (H=100, B=512, L=168) + fc head, 48-step autoregressive rollout.
// Batch is fully independent -> 128 CTAs x 4 batch elems, each CTA runs all
// 48*168 timesteps privately. One thread per gate row (400 threads).
//
// Weights pre-transposed into g_WT[k][r] (k-major, r = gate row, order i,f,g,o):
//   k 0..99   : W_hh0      (layer0 recurrent)
//   k 100..199: W_ih1      (layer1 input-from-h0)
//   k 200..299: W_hh1      (layer1 recurrent)
//   k 300..303: zero pad   (clean 8-wide streamed chunks)
// First NSMROWS k-rows live in smem; the rest stream from L2 each timestep
// with an 8-deep register prefetch (weights stay L2-resident: 486 KB total).

#define HH        100
#define R4        400
#define SEQ       168
#define STEPS     48
#define NBC       4
#define NCTA      128
#define NTHREADS  400
#define NSMROWS   128
#define NROWS_TOT 304
#define NSTREAM   (NROWS_TOT - NSMROWS)   // 176 = 22 * 8

__device__ float g_WT[NROWS_TOT * R4];
__device__ float g_b0[R4], g_b1[R4], g_wx0[R4];
__device__ float g_fc[HH + 1];

// ---------------------------------------------------------------- prep ----
__global__ void prep_kernel(const float* __restrict__ Wih0,
                            const float* __restrict__ Whh0,
                            const float* __restrict__ bih0,
                            const float* __restrict__ bhh0,
                            const float* __restrict__ Wih1,
                            const float* __restrict__ Whh1,
                            const float* __restrict__ bih1,
                            const float* __restrict__ bhh1,
                            const float* __restrict__ fcw,
                            const float* __restrict__ fcb)
{
    int i0 = blockIdx.x * blockDim.x + threadIdx.x;
    int stride = gridDim.x * blockDim.x;
    for (int idx = i0; idx < NROWS_TOT * R4; idx += stride) {
        int k = idx / R4, r = idx - k * R4;
        float v = 0.f;
        if      (k < 100) v = Whh0[r * HH + k];
        else if (k < 200) v = Wih1[r * HH + (k - 100)];
        else if (k < 300) v = Whh1[r * HH + (k - 200)];
        g_WT[idx] = v;
    }
    for (int r = i0; r < R4; r += stride) {
        g_b0[r]  = bih0[r] + bhh0[r];
        g_b1[r]  = bih1[r] + bhh1[r];
        g_wx0[r] = Wih0[r];           // IN == 1
    }
    if (i0 < HH)  g_fc[i0] = fcw[i0];
    if (i0 == HH) g_fc[HH] = fcb[0];
}

// ---------------------------------------------------------------- main ----
__device__ __forceinline__ float sigf(float v) {
    return 1.f / (1.f + __expf(-v));
}

// smem layout (floats):
//   sWT   : NSMROWS*R4            = 51200 f  (204800 B)
//   sHin4 : 204 float4            = 816 f    (hin: h0 | h1 | 0-pad)
//   sG4   : 400 float4            = 1600 f   (gates, [r][b])
//   sC    : 2*100*4               = 800 f    (c0, c1 as [j][b])
//   sXt   : 4 f (align 4) + sY : 4 f
#define SM_WT   0
#define SM_HIN  (NSMROWS * R4)
#define SM_G    (SM_HIN + 204 * 4)
#define SM_C0   (SM_G + R4 * 4)
#define SM_C1   (SM_C0 + HH * 4)
#define SM_XT   (SM_C1 + HH * 4)
#define SM_Y    (SM_XT + 4)
#define SM_TOT  (SM_Y + 4)

__global__ void __launch_bounds__(NTHREADS, 1)
lstm_kernel(const float* __restrict__ x, float* __restrict__ out)
{
    extern __shared__ float sm[];
    float*  sWT   = sm + SM_WT;
    float4* sHin4 = (float4*)(sm + SM_HIN);
    float*  sHinF = sm + SM_HIN;
    float*  sGf   = sm + SM_G;
    float4* sG4   = (float4*)sGf;
    float*  sC0   = sm + SM_C0;
    float*  sC1   = sm + SM_C1;
    float*  sXt   = sm + SM_XT;
    float*  sY    = sm + SM_Y;

    const int tid = threadIdx.x;            // 0..399  (= gate row r)
    const int r   = tid;
    const int bb  = blockIdx.x * NBC;       // batch base

    // load resident weight rows (coalesced)
    for (int i = tid; i < NSMROWS * R4; i += NTHREADS) sWT[i] = g_WT[i];
    // zero state: hin (incl. pad), c0, c1
    for (int i = tid; i < 204 * 4; i += NTHREADS) sHinF[i] = 0.f;
    for (int i = tid; i < HH * 4; i += NTHREADS) { sC0[i] = 0.f; sC1[i] = 0.f; }

    const float wx0 = g_wx0[r];
    const float b0r = g_b0[r];
    const float b1r = g_b1[r];
    const int   jb_b = tid / HH;            // cell-update mapping
    const int   jb_j = tid - jb_b * HH;
    const float* gws = g_WT + NSMROWS * R4 + r;   // streamed base, this column

    __syncthreads();

    for (int s = 0; s < STEPS; s++) {
        for (int t = 0; t < SEQ; t++) {
            // ---- per-timestep scalar input (4 batch elems) ----
            if (tid < NBC) {
                float xv;
                if (s == 0)        xv = x[(bb + tid) * SEQ + t];
                else if (t < SEQ-1) xv = x[(bb + tid) * SEQ + t + 1];
                else                xv = sY[tid];
                sXt[tid] = xv;
            }
            __syncthreads();

            // ================= layer 0 gates =================
            float a0, a1, a2, a3;
            {
                float4 xv4 = *(const float4*)sXt;   // broadcast
                a0 = fmaf(wx0, xv4.x, b0r);
                a1 = fmaf(wx0, xv4.y, b0r);
                a2 = fmaf(wx0, xv4.z, b0r);
                a3 = fmaf(wx0, xv4.w, b0r);
            }
            #pragma unroll 4
            for (int k = 0; k < HH; k++) {
                float  w  = sWT[k * R4 + r];
                float4 h4 = sHin4[k];
                a0 = fmaf(w, h4.x, a0);
                a1 = fmaf(w, h4.y, a1);
                a2 = fmaf(w, h4.z, a2);
                a3 = fmaf(w, h4.w, a3);
            }
            sG4[r] = make_float4(a0, a1, a2, a3);
            __syncthreads();

            // ---- layer 0 cell update ----
            {
                float gi = sGf[ jb_j        * 4 + jb_b];
                float gf = sGf[(jb_j + 100) * 4 + jb_b];
                float gg = sGf[(jb_j + 200) * 4 + jb_b];
                float go = sGf[(jb_j + 300) * 4 + jb_b];
                float c  = sC0[jb_j * 4 + jb_b];
                float cn = sigf(gf) * c + sigf(gi) * tanhf(gg);
                float hn = sigf(go) * tanhf(cn);
                sC0[jb_j * 4 + jb_b]  = cn;
                sHinF[jb_j * 4 + jb_b] = hn;      // hin[0..99] = h0
            }
            __syncthreads();

            // ================= layer 1 gates =================
            a0 = b1r; a1 = b1r; a2 = b1r; a3 = b1r;
            // resident part: p = 0..(NSMROWS-100-1), weight row = 100+p
            #pragma unroll 4
            for (int p = 0; p < NSMROWS - 100; p++) {
                float  w  = sWT[(100 + p) * R4 + r];
                float4 h4 = sHin4[p];
                a0 = fmaf(w, h4.x, a0);
                a1 = fmaf(w, h4.y, a1);
                a2 = fmaf(w, h4.z, a2);
                a3 = fmaf(w, h4.w, a3);
            }
            // streamed part: q = 0..NSTREAM-1, p = (NSMROWS-100)+q
            {
                float wb[8];
                #pragma unroll
                for (int u = 0; u < 8; u++) wb[u] = gws[u * R4];
                #pragma unroll 1
                for (int blk = 0; blk < NSTREAM / 8; blk++) {
                    float wn[8];
                    const float* gn = gws + (blk + 1) * 8 * R4;
                    #pragma unroll
                    for (int u = 0; u < 8; u++)
                        wn[u] = (blk < NSTREAM / 8 - 1) ? gn[u * R4] : 0.f;
                    int pbase = (NSMROWS - 100) + blk * 8;
                    #pragma unroll
                    for (int u = 0; u < 8; u++) {
                        float4 h4 = sHin4[pbase + u];
                        a0 = fmaf(wb[u], h4.x, a0);
                        a1 = fmaf(wb[u], h4.y, a1);
                        a2 = fmaf(wb[u], h4.z, a2);
                        a3 = fmaf(wb[u], h4.w, a3);
                    }
                    #pragma unroll
                    for (int u = 0; u < 8; u++) wb[u] = wn[u];
                }
            }
            sG4[r] = make_float4(a0, a1, a2, a3);
            __syncthreads();

            // ---- layer 1 cell update ----
            {
                float gi = sGf[ jb_j        * 4 + jb_b];
                float gf = sGf[(jb_j + 100) * 4 + jb_b];
                float gg = sGf[(jb_j + 200) * 4 + jb_b];
                float go = sGf[(jb_j + 300) * 4 + jb_b];
                float c  = sC1[jb_j * 4 + jb_b];
                float cn = sigf(gf) * c + sigf(gi) * tanhf(gg);
                float hn = sigf(go) * tanhf(cn);
                sC1[jb_j * 4 + jb_b]           = cn;
                sHinF[(100 + jb_j) * 4 + jb_b] = hn;   // hin[100..199] = h1
            }
            __syncthreads();

            // ---- fc head at sequence end ----
            if (t == SEQ - 1) {
                if (tid < 128) {
                    int b = tid >> 5, l = tid & 31;
                    float p = 0.f;
                    for (int j = l; j < HH; j += 32)
                        p += sHinF[(100 + j) * 4 + b] * g_fc[j];
                    #pragma unroll
                    for (int off = 16; off; off >>= 1)
                        p += __shfl_down_sync(0xffffffffu, p, off);
                    if (l == 0) {
                        float y = p + g_fc[HH];
                        sY[b] = y;
                        out[(bb + b) * STEPS + s] = y;
                    }
                }
                __syncthreads();
            }
        }
    }
}

// -------------------------------------------------------------- launch ----
extern "C" void kernel_launch(void* const* d_in, const int* in_sizes, int n_in,
                              void* d_out, int out_size)
{
    const float* x    = (const float*)d_in[0];
    const float* Wih0 = (const float*)d_in[1];
    const float* Whh0 = (const float*)d_in[2];
    const float* bih0 = (const float*)d_in[3];
    const float* bhh0 = (const float*)d_in[4];
    const float* Wih1 = (const float*)d_in[5];
    const float* Whh1 = (const float*)d_in[6];
    const float* bih1 = (const float*)d_in[7];
    const float* bhh1 = (const float*)d_in[8];
    const float* fcw  = (const float*)d_in[9];
    const float* fcb  = (const float*)d_in[10];
    float* out = (float*)d_out;

    static bool attr_done = false;
    if (!attr_done) {
        cudaFuncSetAttribute(lstm_kernel,
                             cudaFuncAttributeMaxDynamicSharedMemorySize,
                             SM_TOT * (int)sizeof(float));
        attr_done = true;
    }

    prep_kernel<<<128, 256>>>(Wih0, Whh0, bih0, bhh0,
                              Wih1, Whh1, bih1, bhh1, fcw, fcb);
    lstm_kernel<<<NCTA, NTHREADS, SM_TOT * (int)sizeof(float)>>>(x, out);
}